// round 16
// baseline (speedup 1.0000x reference)
#include <cuda_runtime.h>
#include <math.h>

typedef unsigned long long u64;
typedef unsigned int u32;
#define DEVI __device__ __forceinline__

DEVI u64 pack2(float a, float b){ u64 r; asm("mov.b64 %0, {%1,%2};" : "=l"(r) : "f"(a), "f"(b)); return r; }
DEVI void unpack2(u64 v, float& a, float& b){ asm("mov.b64 {%0,%1}, %2;" : "=f"(a), "=f"(b) : "l"(v)); }
DEVI u64 fma2(u64 a, u64 b, u64 c){ u64 d; asm("fma.rn.f32x2 %0, %1, %2, %3;" : "=l"(d) : "l"(a), "l"(b), "l"(c)); return d; }
DEVI u32 cvt_tf32(float f){ u32 r; asm("cvt.rna.tf32.f32 %0, %1;" : "=r"(r) : "f"(f)); return r; }

static const int BATCH = 4096;

// ---- scratch layout (floats), batch-innermost [C][H][W][B] ----
#define OFF_XT  ((size_t)0)                          // [784][B]
#define OFF_A1  (OFF_XT + (size_t)784*4096)          // [32*196][B]
#define OFF_A2  (OFF_A1 + (size_t)6272*4096)         // [32*49][B]
#define OFF_A3  (OFF_A2 + (size_t)1568*4096)         // [1024][B]
#define OFF_MU  (OFF_A3 + (size_t)1024*4096)         // [20][B]
#define OFF_LS  (OFF_MU + (size_t)20*4096)           // [20][B]
#define OFF_ZL  (OFF_LS + (size_t)20*4096)           // [20][B]
#define OFF_D1  (OFF_ZL + (size_t)20*4096)           // [256][B]
#define OFF_D2  (OFF_D1 + (size_t)256*4096)          // [1024][B]
#define OFF_D3  (OFF_D2 + (size_t)1024*4096)         // [32*49][B]
#define OFF_D4  (OFF_D3 + (size_t)1568*4096)         // [32*196][B]
#define OFF_FCP (OFF_D4 + (size_t)6272*4096)         // [2][256][B] fc1 split-K partials
#define SCRATCH_TOTAL (OFF_FCP + (size_t)2*256*4096)

__device__ __align__(256) float g_scratch[SCRATCH_TOTAL];

// ---------------- generic transpose [R][C] -> [C][R] ----------------
__global__ void transpose_k(const float* __restrict__ in, float* __restrict__ out, int R, int C){
    __shared__ float t[32][33];
    int c = blockIdx.x*32 + threadIdx.x;
    int r = blockIdx.y*32 + threadIdx.y;
    if (r < R && c < C) t[threadIdx.y][threadIdx.x] = in[(size_t)r*C + c];
    __syncthreads();
    int c2 = blockIdx.x*32 + threadIdx.y;
    int r2 = blockIdx.y*32 + threadIdx.x;
    if (r2 < R && c2 < C) out[(size_t)c2*R + r2] = t[threadIdx.x][threadIdx.y];
}

// ================= mma.sync tf32 GEMM, tf32x2 split (proven) =================
// out[m][b] = relu?(bias[m] + sum_k W[m][k] * Act[k][b])   (Act is [KTOT][4096])
template<int KTOT, bool RELU, int MTOT, int KSPLIT>
__global__ void __launch_bounds__(256) gemm_mma(
    const float* __restrict__ Act, const float* __restrict__ W,
    const float* __restrict__ bias, float* __restrict__ out)
{
    __shared__ __align__(16) float sAh[16*132];
    __shared__ __align__(16) float sAl[16*132];
    __shared__ __align__(16) float sB [64*66];

    const int tid = threadIdx.x;
    const int lane = tid & 31, wid = tid >> 5;
    const int wm = wid & 1, wn = wid >> 1;
    const int group = lane >> 2, tig = lane & 3;
    const int m0 = blockIdx.y * 64;
    const int b0 = blockIdx.x * 128;
    const int ks = blockIdx.z;
    constexpr int CPK = KTOT/32/KSPLIT;
    if (KSPLIT > 1) out += (size_t)ks * MTOT * 4096;

    float acc[2][4][4];
    #pragma unroll
    for (int i=0;i<2;i++) for (int j=0;j<4;j++) for (int q=0;q<4;q++) acc[i][j][q] = 0.0f;

    for (int kc = ks*CPK; kc < (ks+1)*CPK; kc++){
        #pragma unroll
        for (int it=0; it<2; it++){
            int idx = tid + it*256;
            int m = idx >> 3, kq = (idx & 7) * 4;
            float4 v = *reinterpret_cast<const float4*>(W + (size_t)(m0+m)*KTOT + kc*32 + kq);
            int tm = m >> 4, row = m & 15;
            float vv[4] = {v.x, v.y, v.z, v.w};
            #pragma unroll
            for (int j=0;j<4;j++){
                int k = kq + j, tk = k >> 3, col = k & 7;
                int lane_s = ((row & 7) << 2) | (col & 3);
                int reg = ((row >> 3) & 1) | ((col >> 2) << 1);
                int off = (tm*4 + tk)*132 + lane_s*4 + reg;
                u32 hi = cvt_tf32(vv[j]);
                *reinterpret_cast<u32*>(&sAh[off]) = hi;
                *reinterpret_cast<u32*>(&sAl[off]) = cvt_tf32(vv[j] - __uint_as_float(hi));
            }
        }
        #pragma unroll
        for (int it=0; it<4; it++){
            int idx = tid + it*256;
            int kr = idx >> 5;
            int nq = (idx & 31) * 4;
            float4 v = *reinterpret_cast<const float4*>(Act + (size_t)(kc*32 + kr)*4096 + b0 + nq);
            int tk = kr >> 3, rowk = kr & 7;
            float vv[4] = {v.x, v.y, v.z, v.w};
            #pragma unroll
            for (int j=0;j<4;j++){
                int n = nq + j;
                sB[((n>>3)*4 + tk)*66 + (((n&7)<<2)|(rowk&3))*2 + (rowk>>2)] = vv[j];
            }
        }
        __syncthreads();

        #pragma unroll
        for (int tk=0; tk<4; tk++){
            u32 afh[2][4], afl[2][4];
            u32 bfh[4][2], bfl[4][2];
            #pragma unroll
            for (int i=0;i<2;i++){
                int base = ((wm*2+i)*4 + tk)*132 + lane*4;
                const float4 h4 = *reinterpret_cast<const float4*>(&sAh[base]);
                const float4 l4 = *reinterpret_cast<const float4*>(&sAl[base]);
                afh[i][0]=__float_as_uint(h4.x); afh[i][1]=__float_as_uint(h4.y);
                afh[i][2]=__float_as_uint(h4.z); afh[i][3]=__float_as_uint(h4.w);
                afl[i][0]=__float_as_uint(l4.x); afl[i][1]=__float_as_uint(l4.y);
                afl[i][2]=__float_as_uint(l4.z); afl[i][3]=__float_as_uint(l4.w);
            }
            #pragma unroll
            for (int j=0;j<4;j++){
                const float2 t2 = *reinterpret_cast<const float2*>(&sB[((wn*4+j)*4 + tk)*66 + lane*2]);
                float tv[2] = {t2.x, t2.y};
                #pragma unroll
                for (int q=0;q<2;q++){
                    u32 hi = cvt_tf32(tv[q]);
                    bfh[j][q] = hi;
                    bfl[j][q] = cvt_tf32(tv[q] - __uint_as_float(hi));
                }
            }
            #pragma unroll
            for (int i=0;i<2;i++)
                #pragma unroll
                for (int j=0;j<4;j++){
                    asm volatile(
                        "mma.sync.aligned.m16n8k8.row.col.f32.tf32.tf32.f32 "
                        "{%0,%1,%2,%3}, {%4,%5,%6,%7}, {%8,%9}, {%0,%1,%2,%3};"
                        : "+f"(acc[i][j][0]), "+f"(acc[i][j][1]), "+f"(acc[i][j][2]), "+f"(acc[i][j][3])
                        : "r"(afh[i][0]), "r"(afh[i][1]), "r"(afh[i][2]), "r"(afh[i][3]),
                          "r"(bfl[j][0]), "r"(bfl[j][1]));
                    asm volatile(
                        "mma.sync.aligned.m16n8k8.row.col.f32.tf32.tf32.f32 "
                        "{%0,%1,%2,%3}, {%4,%5,%6,%7}, {%8,%9}, {%0,%1,%2,%3};"
                        : "+f"(acc[i][j][0]), "+f"(acc[i][j][1]), "+f"(acc[i][j][2]), "+f"(acc[i][j][3])
                        : "r"(afl[i][0]), "r"(afl[i][1]), "r"(afl[i][2]), "r"(afl[i][3]),
                          "r"(bfh[j][0]), "r"(bfh[j][1]));
                    asm volatile(
                        "mma.sync.aligned.m16n8k8.row.col.f32.tf32.tf32.f32 "
                        "{%0,%1,%2,%3}, {%4,%5,%6,%7}, {%8,%9}, {%0,%1,%2,%3};"
                        : "+f"(acc[i][j][0]), "+f"(acc[i][j][1]), "+f"(acc[i][j][2]), "+f"(acc[i][j][3])
                        : "r"(afh[i][0]), "r"(afh[i][1]), "r"(afh[i][2]), "r"(afh[i][3]),
                          "r"(bfh[j][0]), "r"(bfh[j][1]));
                }
        }
        __syncthreads();
    }

    #pragma unroll
    for (int i=0;i<2;i++){
        int mA = m0 + wm*32 + i*16 + group;
        int mB = mA + 8;
        float bA = (KSPLIT==1) ? bias[mA] : 0.0f;
        float bB = (KSPLIT==1) ? bias[mB] : 0.0f;
        #pragma unroll
        for (int j=0;j<4;j++){
            int n = b0 + wn*32 + j*8 + tig*2;
            float r0 = acc[i][j][0] + bA, r1 = acc[i][j][1] + bA;
            float r2 = acc[i][j][2] + bB, r3 = acc[i][j][3] + bB;
            if (RELU && KSPLIT==1){
                r0 = fmaxf(r0,0.0f); r1 = fmaxf(r1,0.0f);
                r2 = fmaxf(r2,0.0f); r3 = fmaxf(r3,0.0f);
            }
            *reinterpret_cast<float2*>(out + (size_t)mA*4096 + n) = make_float2(r0, r1);
            *reinterpret_cast<float2*>(out + (size_t)mB*4096 + n) = make_float2(r2, r3);
        }
    }
}

// ================= conv/deconv as gather-GEMM, gemm_mma-shaped tile =================
// COUT=32 (2 m-tiles). Warps 2(m) x 4(n), N tile = 128 batch. smem ~25KB -> 3-4 CTAs/SM.
// Per-pixel tap table; every 32-K chunk maps to a fixed tap (CIN multiple of 32).
template<int CINL2, int KDIM, int HIN, int WIN, int HOUT, int WOUT,
         int STRIDE, int PAD, bool DECONV>
__global__ void __launch_bounds__(256) convgemm(
    const float* __restrict__ in, const float* __restrict__ wt,
    const float* __restrict__ bias, float* __restrict__ out)
{
    constexpr int CIN = 1 << CINL2;
    constexpr int COUT = 32;
    constexpr int KK2 = KDIM*KDIM;
    __shared__ __align__(16) float sAh[8*132];
    __shared__ __align__(16) float sAl[8*132];
    __shared__ __align__(16) float sB [64*66];
    __shared__ int s_pix[KK2], s_kk[KK2];
    __shared__ int s_nt;

    const int tid = threadIdx.x;
    const int lane = tid & 31, wid = tid >> 5;
    const int wm = wid & 1, wn = wid >> 1;
    const int group = lane >> 2, tig = lane & 3;
    const int b0 = blockIdx.x * 128;
    const int p  = blockIdx.y;
    const int oy = p / WOUT, ox = p % WOUT;

    if (tid == 0){
        int nt = 0;
        for (int ky=0; ky<KDIM; ky++)
        for (int kx=0; kx<KDIM; kx++){
            int iy, ix; bool v;
            if (DECONV){
                int ty = oy + PAD - ky, tx = ox + PAD - kx;
                v = (ty>=0) && (tx>=0) && ((ty % STRIDE)==0) && ((tx % STRIDE)==0);
                iy = ty / STRIDE; ix = tx / STRIDE;
                v = v && iy < HIN && ix < WIN;
            } else {
                iy = oy*STRIDE - PAD + ky; ix = ox*STRIDE - PAD + kx;
                v = iy>=0 && iy<HIN && ix>=0 && ix<WIN;
            }
            if (v){ s_pix[nt] = iy*WIN + ix; s_kk[nt] = ky*KDIM + kx; nt++; }
        }
        s_nt = nt;
    }
    __syncthreads();
    const int NC = (s_nt << CINL2) >> 5;

    float acc[4][4];
    #pragma unroll
    for (int j=0;j<4;j++) for (int q=0;q<4;q++) acc[j][q] = 0.0f;

    for (int c = 0; c < NC; c++){
        const int kbase = c*32;
        // ---- A fill: 32 oc x 32 k (weight gather), 4 elements/thread ----
        #pragma unroll
        for (int it=0; it<4; it++){
            int idx = tid + it*256;
            int m = idx >> 5, kr = idx & 31;
            int k = kbase + kr;
            int t = k >> CINL2, ic = k & (CIN-1);
            int kkv = s_kk[t];
            int g = DECONV ? ((ic*COUT + m)*KK2 + kkv) : ((m*CIN + ic)*KK2 + kkv);
            float w = wt[g];
            int tm = m >> 4, row = m & 15, tk = kr >> 3, col = kr & 7;
            int lane_s = ((row & 7) << 2) | (col & 3);
            int reg = ((row >> 3) & 1) | ((col >> 2) << 1);
            int off = (tm*4 + tk)*132 + lane_s*4 + reg;
            u32 hi = cvt_tf32(w);
            *reinterpret_cast<u32*>(&sAh[off]) = hi;
            *reinterpret_cast<u32*>(&sAl[off]) = cvt_tf32(w - __uint_as_float(hi));
        }
        // ---- B fill: 32 k-rows x 128 batch, tap gather, coalesced float4 ----
        #pragma unroll
        for (int it=0; it<4; it++){
            int idx = tid + it*256;
            int kr = idx >> 5;
            int nq = (idx & 31) * 4;
            int k = kbase + kr;
            int t = k >> CINL2, ic = k & (CIN-1);
            int pix = s_pix[t];
            float4 v = *reinterpret_cast<const float4*>(in + ((size_t)(ic*(HIN*WIN) + pix))*4096 + b0 + nq);
            int tk = kr >> 3, rowk = kr & 7;
            float vv[4] = {v.x, v.y, v.z, v.w};
            #pragma unroll
            for (int j=0;j<4;j++){
                int n = nq + j;
                sB[((n>>3)*4 + tk)*66 + (((n&7)<<2)|(rowk&3))*2 + (rowk>>2)] = vv[j];
            }
        }
        __syncthreads();

        #pragma unroll
        for (int tk=0; tk<4; tk++){
            u32 afh[4], afl[4];
            u32 bfh[4][2], bfl[4][2];
            {
                int base = (wm*4 + tk)*132 + lane*4;
                const float4 h4 = *reinterpret_cast<const float4*>(&sAh[base]);
                const float4 l4 = *reinterpret_cast<const float4*>(&sAl[base]);
                afh[0]=__float_as_uint(h4.x); afh[1]=__float_as_uint(h4.y);
                afh[2]=__float_as_uint(h4.z); afh[3]=__float_as_uint(h4.w);
                afl[0]=__float_as_uint(l4.x); afl[1]=__float_as_uint(l4.y);
                afl[2]=__float_as_uint(l4.z); afl[3]=__float_as_uint(l4.w);
            }
            #pragma unroll
            for (int j=0;j<4;j++){
                const float2 t2 = *reinterpret_cast<const float2*>(&sB[((wn*4+j)*4 + tk)*66 + lane*2]);
                float tv[2] = {t2.x, t2.y};
                #pragma unroll
                for (int q=0;q<2;q++){
                    u32 hi = cvt_tf32(tv[q]);
                    bfh[j][q] = hi;
                    bfl[j][q] = cvt_tf32(tv[q] - __uint_as_float(hi));
                }
            }
            #pragma unroll
            for (int j=0;j<4;j++){
                asm volatile(
                    "mma.sync.aligned.m16n8k8.row.col.f32.tf32.tf32.f32 "
                    "{%0,%1,%2,%3}, {%4,%5,%6,%7}, {%8,%9}, {%0,%1,%2,%3};"
                    : "+f"(acc[j][0]), "+f"(acc[j][1]), "+f"(acc[j][2]), "+f"(acc[j][3])
                    : "r"(afh[0]), "r"(afh[1]), "r"(afh[2]), "r"(afh[3]),
                      "r"(bfl[j][0]), "r"(bfl[j][1]));
                asm volatile(
                    "mma.sync.aligned.m16n8k8.row.col.f32.tf32.tf32.f32 "
                    "{%0,%1,%2,%3}, {%4,%5,%6,%7}, {%8,%9}, {%0,%1,%2,%3};"
                    : "+f"(acc[j][0]), "+f"(acc[j][1]), "+f"(acc[j][2]), "+f"(acc[j][3])
                    : "r"(afl[0]), "r"(afl[1]), "r"(afl[2]), "r"(afl[3]),
                      "r"(bfh[j][0]), "r"(bfh[j][1]));
                asm volatile(
                    "mma.sync.aligned.m16n8k8.row.col.f32.tf32.tf32.f32 "
                    "{%0,%1,%2,%3}, {%4,%5,%6,%7}, {%8,%9}, {%0,%1,%2,%3};"
                    : "+f"(acc[j][0]), "+f"(acc[j][1]), "+f"(acc[j][2]), "+f"(acc[j][3])
                    : "r"(afh[0]), "r"(afh[1]), "r"(afh[2]), "r"(afh[3]),
                      "r"(bfh[j][0]), "r"(bfh[j][1]));
            }
        }
        __syncthreads();
    }

    {
        int mA = wm*16 + group;
        int mB = mA + 8;
        float bA = bias[mA], bB = bias[mB];
        #pragma unroll
        for (int j=0;j<4;j++){
            int n = b0 + wn*32 + j*8 + tig*2;
            float r0 = fmaxf(acc[j][0] + bA, 0.0f);
            float r1 = fmaxf(acc[j][1] + bA, 0.0f);
            float r2 = fmaxf(acc[j][2] + bB, 0.0f);
            float r3 = fmaxf(acc[j][3] + bB, 0.0f);
            *reinterpret_cast<float2*>(out + ((size_t)(mA*(HOUT*WOUT) + p))*4096 + n) = make_float2(r0, r1);
            *reinterpret_cast<float2*>(out + ((size_t)(mB*(HOUT*WOUT) + p))*4096 + n) = make_float2(r2, r3);
        }
    }
}

// ---------------- scalar conv kernel (conv1, conv3, fc2) ----------------
template<int CIN,int COUT,int K,int HIN,int WIN,int HOUT,int WOUT,int STRIDE,int PAD,
         bool DECONV,int OCC,int VEC,int ICC,int ACT>
__global__ void __launch_bounds__(256) convk(
    const float* __restrict__ in, const float* __restrict__ wt,
    const float* __restrict__ bias, float* __restrict__ out)
{
    static_assert(CIN % ICC == 0, "ICC must divide CIN");
    constexpr int KK = K*K;
    const int p  = blockIdx.y;
    const int oy = p / WOUT, ox = p % WOUT;
    const int oc0 = blockIdx.z * OCC;
    const int b  = (blockIdx.x * 256 + threadIdx.x) * VEC;

    __shared__ u64 sw[OCC*ICC*KK];

    u64 acc[OCC][VEC/2];
    #pragma unroll
    for (int j=0;j<OCC;j++){
        float bv = bias[oc0 + j];
        u64 bp = pack2(bv,bv);
        #pragma unroll
        for (int v=0;v<VEC/2;v++) acc[j][v] = bp;
    }

    for (int ic0 = 0; ic0 < CIN; ic0 += ICC){
        __syncthreads();
        for (int i = threadIdx.x; i < OCC*ICC*KK; i += 256){
            int jo = i / (ICC*KK);
            int ic = (i / KK) % ICC;
            int kk = i % KK;
            int g  = DECONV ? (((ic0+ic)*COUT + (oc0+jo))*KK + kk)
                            : (((oc0+jo)*CIN + (ic0+ic))*KK + kk);
            float w = wt[g];
            sw[i] = pack2(w, w);
        }
        __syncthreads();

        #pragma unroll
        for (int ky=0; ky<K; ky++){
            int iy; bool vy;
            if (DECONV){ int t = oy + PAD - ky; vy = (t>=0) && ((t % STRIDE)==0); iy = t / STRIDE; vy = vy && (iy < HIN); }
            else       { iy = oy*STRIDE - PAD + ky; vy = (iy>=0) && (iy < HIN); }
            if (!vy) continue;
            #pragma unroll
            for (int kx=0; kx<K; kx++){
                int ix; bool vx;
                if (DECONV){ int t = ox + PAD - kx; vx = (t>=0) && ((t % STRIDE)==0); ix = t / STRIDE; vx = vx && (ix < WIN); }
                else       { ix = ox*STRIDE - PAD + kx; vx = (ix>=0) && (ix < WIN); }
                if (!vx) continue;
                const int kk = ky*K + kx;
                const float* ipbase = in + ((size_t)(iy*WIN + ix))*BATCH + b;
                #pragma unroll 4
                for (int ic=0; ic<ICC; ic++){
                    const float* ip = ipbase + (size_t)(ic0+ic)*(HIN*WIN)*BATCH;
                    u64 v[VEC/2];
                    if constexpr (VEC == 4){
                        ulonglong2 u = *reinterpret_cast<const ulonglong2*>(ip);
                        v[0] = u.x; v[1] = u.y;
                    } else {
                        v[0] = *reinterpret_cast<const u64*>(ip);
                    }
                    #pragma unroll
                    for (int j=0;j<OCC;j++){
                        u64 wv = sw[(j*ICC + ic)*KK + kk];
                        #pragma unroll
                        for (int h=0; h<VEC/2; h++) acc[j][h] = fma2(v[h], wv, acc[j][h]);
                    }
                }
            }
        }
    }

    #pragma unroll
    for (int j=0;j<OCC;j++){
        float vals[VEC];
        #pragma unroll
        for (int h=0; h<VEC/2; h++){
            float a_, b_; unpack2(acc[j][h], a_, b_);
            vals[2*h] = a_; vals[2*h+1] = b_;
        }
        #pragma unroll
        for (int q=0; q<VEC; q++){
            if (ACT == 1) vals[q] = fmaxf(vals[q], 0.0f);
            else if (ACT == 2) vals[q] = 1.0f / (1.0f + __expf(-vals[q]));
        }
        float* op = out + ((size_t)((oc0+j)*(HOUT*WOUT) + p))*BATCH + b;
        if constexpr (VEC == 4) *reinterpret_cast<float4*>(op) = make_float4(vals[0],vals[1],vals[2],vals[3]);
        else                    *reinterpret_cast<float2*>(op) = make_float2(vals[0],vals[1]);
    }
}

// ---------------- fused fc1-reduce + mu/ls heads ----------------
__global__ void __launch_bounds__(256) muls_k(
    const float* __restrict__ part, const float* __restrict__ bfc1,
    const float* __restrict__ wmu, const float* __restrict__ bmu,
    const float* __restrict__ wls, const float* __restrict__ bls,
    float* __restrict__ muB, float* __restrict__ lsB)
{
    __shared__ u64 swm[4*256];
    __shared__ u64 swl[4*256];
    __shared__ float sbias[256];
    const int l0 = blockIdx.z * 4;
    for (int i = threadIdx.x; i < 4*256; i += 256){
        int l = i >> 8, k = i & 255;
        float a = wmu[(l0+l)*256 + k]; swm[i] = pack2(a,a);
        float c = wls[(l0+l)*256 + k]; swl[i] = pack2(c,c);
    }
    if (threadIdx.x < 256) sbias[threadIdx.x] = bfc1[threadIdx.x];
    __syncthreads();

    const int b = (blockIdx.x*256 + threadIdx.x) * 4;
    u64 am[4][2], al[4][2];
    #pragma unroll
    for (int j=0;j<4;j++){
        float bm = bmu[l0+j], bl2 = bls[l0+j];
        am[j][0] = pack2(bm,bm); am[j][1] = am[j][0];
        al[j][0] = pack2(bl2,bl2); al[j][1] = al[j][0];
    }
    const float* p0 = part;
    const float* p1 = part + (size_t)256*4096;
    #pragma unroll 2
    for (int k=0;k<256;k++){
        float4 q0 = *reinterpret_cast<const float4*>(p0 + (size_t)k*4096 + b);
        float4 q1 = *reinterpret_cast<const float4*>(p1 + (size_t)k*4096 + b);
        float bv = sbias[k];
        float h0 = fmaxf(q0.x + q1.x + bv, 0.0f);
        float h1 = fmaxf(q0.y + q1.y + bv, 0.0f);
        float h2 = fmaxf(q0.z + q1.z + bv, 0.0f);
        float h3 = fmaxf(q0.w + q1.w + bv, 0.0f);
        u64 hx = pack2(h0, h1), hy = pack2(h2, h3);
        #pragma unroll
        for (int j=0;j<4;j++){
            u64 wm = swm[j*256 + k], wl = swl[j*256 + k];
            am[j][0] = fma2(hx, wm, am[j][0]);
            am[j][1] = fma2(hy, wm, am[j][1]);
            al[j][0] = fma2(hx, wl, al[j][0]);
            al[j][1] = fma2(hy, wl, al[j][1]);
        }
    }
    #pragma unroll
    for (int j=0;j<4;j++){
        float m0,m1,m2,m3, s0,s1,s2,s3;
        unpack2(am[j][0], m0,m1); unpack2(am[j][1], m2,m3);
        unpack2(al[j][0], s0,s1); unpack2(al[j][1], s2,s3);
        float* mp = muB + (size_t)(l0+j)*4096 + b;
        float* sp = lsB + (size_t)(l0+j)*4096 + b;
        *reinterpret_cast<float4*>(mp) = make_float4(m0,m1,m2,m3);
        *reinterpret_cast<float4*>(sp) = make_float4(s0,s1,s2,s3);
    }
}

// ---------------- specialized deconv3 (32->1, sigmoid) + fused output transpose ----
__global__ void __launch_bounds__(256,4) deconv3_k(
    const float* __restrict__ in, const float* __restrict__ wt,
    const float* __restrict__ bias, float* __restrict__ out) // out: [B][784]
{
    __shared__ __align__(16) u64 sw[32*16];
    for (int i = threadIdx.x; i < 512; i += 256){ float w = wt[i]; sw[i] = pack2(w,w); }
    __syncthreads();

    const int t  = blockIdx.y % 7;
    const int oy = blockIdx.y / 7;
    const int b  = (blockIdx.x*256 + threadIdx.x) * 4;

    float bv = bias[0];
    u64 bp = pack2(bv,bv);
    u64 acc[4][2];
    #pragma unroll
    for (int p2=0;p2<4;p2++){ acc[p2][0]=bp; acc[p2][1]=bp; }

    const bool v0 = (2*t-1) >= 0;
    const bool v3 = (2*t+2) < 14;
    const int ky0 = (oy + 1) & 1;

    #pragma unroll
    for (int kyi=0; kyi<2; kyi++){
        const int ky = ky0 + 2*kyi;
        const int iy = (oy + 1 - ky) >> 1;
        if (iy < 0 || iy >= 14) continue;
        for (int ic=0; ic<32; ic++){
            const float* ipb = in + ((size_t)(ic*196 + iy*14 + 2*t - 1))*BATCH + b;
            u64 L[4][2];
            #pragma unroll
            for (int k=0;k<4;k++){
                bool valid = (k==0) ? v0 : (k==3 ? v3 : true);
                if (valid){
                    ulonglong2 u = *reinterpret_cast<const ulonglong2*>(ipb + (size_t)k*BATCH);
                    L[k][0]=u.x; L[k][1]=u.y;
                } else { L[k][0]=0; L[k][1]=0; }
            }
            const u64* wb = &sw[ic*16 + ky*4];
            u64 w0=wb[0], w1=wb[1], w2=wb[2], w3=wb[3];
            #pragma unroll
            for (int h=0;h<2;h++){
                acc[0][h] = fma2(L[1][h], w1, acc[0][h]);
                acc[0][h] = fma2(L[0][h], w3, acc[0][h]);
                acc[1][h] = fma2(L[2][h], w0, acc[1][h]);
                acc[1][h] = fma2(L[1][h], w2, acc[1][h]);
                acc[2][h] = fma2(L[2][h], w1, acc[2][h]);
                acc[2][h] = fma2(L[1][h], w3, acc[2][h]);
                acc[3][h] = fma2(L[3][h], w0, acc[3][h]);
                acc[3][h] = fma2(L[2][h], w2, acc[3][h]);
            }
        }
    }

    float vals[4][4];
    #pragma unroll
    for (int p2=0;p2<4;p2++){
        unpack2(acc[p2][0], vals[p2][0], vals[p2][1]);
        unpack2(acc[p2][1], vals[p2][2], vals[p2][3]);
        #pragma unroll
        for (int q=0;q<4;q++) vals[p2][q] = 1.0f / (1.0f + __expf(-vals[p2][q]));
    }
    const int pbase = oy*28 + 4*t;
    #pragma unroll
    for (int bi=0; bi<4; bi++){
        float* op = out + (size_t)(b + bi)*784 + pbase;
        *reinterpret_cast<float4*>(op) = make_float4(vals[0][bi], vals[1][bi], vals[2][bi], vals[3][bi]);
    }
}

// ---------------- latent: 100-step recursion ----------------
__global__ void latent_k(const float* __restrict__ mu, const float* __restrict__ ls,
                         const float* __restrict__ eps, float* __restrict__ zl,
                         float* __restrict__ outMu, float* __restrict__ outLv)
{
    int i = blockIdx.x*256 + threadIdx.x;
    if (i >= 20*BATCH) return;
    int l = i / BATCH, b = i % BATCH;
    float m = mu[i];
    float s = ls[i];
    outMu[(size_t)b*20 + l] = m;
    outLv[(size_t)b*20 + l] = s;
    float mr = m, sr = s;
    #pragma unroll 5
    for (int k=0;k<100;k++){
        mr = mr + 0.1f*mr;
        sr = sr + 0.05f*(__expf(sr) - 1.0f);
    }
    zl[i] = eps[(size_t)b*20 + l] * __expf(0.5f*sr) + mr;
}

extern "C" void kernel_launch(void* const* d_in, const int* in_sizes, int n_in,
                              void* d_out, int out_size)
{
    const float* x    = (const float*)d_in[0];
    const float* eps  = (const float*)d_in[1];
    const float* w_c1 = (const float*)d_in[2];  const float* b_c1 = (const float*)d_in[3];
    const float* w_c2 = (const float*)d_in[4];  const float* b_c2 = (const float*)d_in[5];
    const float* w_c3 = (const float*)d_in[6];  const float* b_c3 = (const float*)d_in[7];
    const float* w_fc1= (const float*)d_in[8];  const float* b_fc1= (const float*)d_in[9];
    const float* w_mu = (const float*)d_in[10]; const float* b_mu = (const float*)d_in[11];
    const float* w_ls = (const float*)d_in[12]; const float* b_ls = (const float*)d_in[13];
    const float* w_fc2= (const float*)d_in[14]; const float* b_fc2= (const float*)d_in[15];
    const float* w_fc3= (const float*)d_in[16]; const float* b_fc3= (const float*)d_in[17];
    const float* w_d1 = (const float*)d_in[18]; const float* b_d1 = (const float*)d_in[19];
    const float* w_d2 = (const float*)d_in[20]; const float* b_d2 = (const float*)d_in[21];
    const float* w_d3 = (const float*)d_in[22]; const float* b_d3 = (const float*)d_in[23];
    float* out = (float*)d_out;

    float* S = nullptr;
    cudaGetSymbolAddress((void**)&S, g_scratch);

    float* xT = S + OFF_XT;
    float* a1 = S + OFF_A1;
    float* a2 = S + OFF_A2;
    float* a3 = S + OFF_A3;
    float* muB= S + OFF_MU;
    float* lsB= S + OFF_LS;
    float* zl = S + OFF_ZL;
    float* d1h= S + OFF_D1;
    float* d2h= S + OFF_D2;
    float* d3 = S + OFF_D3;
    float* d4 = S + OFF_D4;
    float* fcp= S + OFF_FCP;

    float* outMu = out + (size_t)BATCH*784;
    float* outLv = outMu + (size_t)BATCH*20;

    dim3 tb(32,32);
    transpose_k<<<dim3(25,128), tb>>>(x, xT, 4096, 784);

    // encoder
    convk<1,  32, 4, 28,28, 14,14, 2,1, false, 16,4, 1,  1><<<dim3(4,196,2), 256>>>(xT,  w_c1, b_c1, a1);
    convgemm<5, 4, 14,14, 7, 7, 2,1, false><<<dim3(32,49), 256>>>(a1, w_c2, b_c2, a2);
    convk<32, 64, 3, 7, 7,  4, 4,  2,1, false, 8, 4, 32, 1><<<dim3(4,16, 8), 256>>>(a2,  w_c3, b_c3, a3);

    // fc1 on mma.sync tf32x2 split, direct [K][B] read, split-K=2
    gemm_mma<1024,false,256,2><<<dim3(32,4,2), 256>>>(a3, w_fc1, b_fc1, fcp);

    // fused fc1-reduce + mu/ls heads
    muls_k<<<dim3(4,1,5), 256>>>(fcp, b_fc1, w_mu, b_mu, w_ls, b_ls, muB, lsB);

    latent_k<<<(20*BATCH + 255)/256, 256>>>(muB, lsB, eps, zl, outMu, outLv);

    // decoder
    convk<20, 256, 1, 1,1,  1, 1,  1,0, false, 16,4, 20, 1><<<dim3(4,1, 16), 256>>>(zl,  w_fc2,b_fc2,d1h);
    gemm_mma<256,true,1024,1><<<dim3(32,16,1), 256>>>(d1h, w_fc3, b_fc3, d2h);

    convgemm<6, 3, 4, 4, 7, 7, 2,1, true><<<dim3(32,49), 256>>>(d2h, w_d1, b_d1, d3);
    convgemm<5, 4, 7, 7, 14,14, 2,1, true><<<dim3(32,196), 256>>>(d3,  w_d2, b_d2, d4);
    deconv3_k<<<dim3(4,196), 256>>>(d4, w_d3, b_d3, out);
}

// round 17
// speedup vs baseline: 1.0942x; 1.0942x over previous
#include <cuda_runtime.h>
#include <math.h>

typedef unsigned long long u64;
typedef unsigned int u32;
#define DEVI __device__ __forceinline__

DEVI u64 pack2(float a, float b){ u64 r; asm("mov.b64 %0, {%1,%2};" : "=l"(r) : "f"(a), "f"(b)); return r; }
DEVI void unpack2(u64 v, float& a, float& b){ asm("mov.b64 {%0,%1}, %2;" : "=f"(a), "=f"(b) : "l"(v)); }
DEVI u64 fma2(u64 a, u64 b, u64 c){ u64 d; asm("fma.rn.f32x2 %0, %1, %2, %3;" : "=l"(d) : "l"(a), "l"(b), "l"(c)); return d; }
DEVI u32 cvt_tf32(float f){ u32 r; asm("cvt.rna.tf32.f32 %0, %1;" : "=r"(r) : "f"(f)); return r; }

static const int BATCH = 4096;

// ---- scratch layout (floats), batch-innermost [C][H][W][B] ----
#define OFF_XT  ((size_t)0)                          // [784][B]
#define OFF_A1  (OFF_XT + (size_t)784*4096)          // [32*196][B]
#define OFF_A2  (OFF_A1 + (size_t)6272*4096)         // [32*49][B]
#define OFF_A3  (OFF_A2 + (size_t)1568*4096)         // [1024][B]
#define OFF_MU  (OFF_A3 + (size_t)1024*4096)         // [20][B]
#define OFF_LS  (OFF_MU + (size_t)20*4096)           // [20][B]
#define OFF_ZL  (OFF_LS + (size_t)20*4096)           // [20][B]
#define OFF_D1  (OFF_ZL + (size_t)20*4096)           // [256][B]
#define OFF_D2  (OFF_D1 + (size_t)256*4096)          // [1024][B]
#define OFF_D3  (OFF_D2 + (size_t)1024*4096)         // [32*49][B]
#define OFF_D4  (OFF_D3 + (size_t)1568*4096)         // [32*196][B]
#define OFF_FCP (OFF_D4 + (size_t)6272*4096)         // [2][256][B] fc1 split-K partials
#define SCRATCH_TOTAL (OFF_FCP + (size_t)2*256*4096)

__device__ __align__(256) float g_scratch[SCRATCH_TOTAL];

// ---------------- generic transpose [R][C] -> [C][R] ----------------
__global__ void transpose_k(const float* __restrict__ in, float* __restrict__ out, int R, int C){
    __shared__ float t[32][33];
    int c = blockIdx.x*32 + threadIdx.x;
    int r = blockIdx.y*32 + threadIdx.y;
    if (r < R && c < C) t[threadIdx.y][threadIdx.x] = in[(size_t)r*C + c];
    __syncthreads();
    int c2 = blockIdx.x*32 + threadIdx.y;
    int r2 = blockIdx.y*32 + threadIdx.x;
    if (r2 < R && c2 < C) out[(size_t)c2*R + r2] = t[threadIdx.x][threadIdx.y];
}

// ================= mma.sync tf32 GEMM, tf32x2 split, software-pipelined =================
// out[m][b] = relu?(bias[m] + sum_k W[m][k] * Act[k][b])   (Act is [KTOT][4096])
// Per chunk: store regs->smem; sync; prefetch next chunk LDGs; MMA; sync.
template<int KTOT, bool RELU, int MTOT, int KSPLIT>
__global__ void __launch_bounds__(256) gemm_mma(
    const float* __restrict__ Act, const float* __restrict__ W,
    const float* __restrict__ bias, float* __restrict__ out)
{
    __shared__ __align__(16) float sAh[16*132];
    __shared__ __align__(16) float sAl[16*132];
    __shared__ __align__(16) float sB [64*66];

    const int tid = threadIdx.x;
    const int lane = tid & 31, wid = tid >> 5;
    const int wm = wid & 1, wn = wid >> 1;
    const int group = lane >> 2, tig = lane & 3;
    const int m0 = blockIdx.y * 64;
    const int b0 = blockIdx.x * 128;
    const int ks = blockIdx.z;
    constexpr int CPK = KTOT/32/KSPLIT;
    if (KSPLIT > 1) out += (size_t)ks * MTOT * 4096;

    float acc[2][4][4];
    #pragma unroll
    for (int i=0;i<2;i++) for (int j=0;j<4;j++) for (int q=0;q<4;q++) acc[i][j][q] = 0.0f;

    // per-thread fixed fill coordinates
    const int a_m0  = tid >> 3, a_kq = (tid & 7) * 4;        // + it*32 rows
    const int b_kr0 = tid >> 5, b_nq = (tid & 31) * 4;       // + it*8  k-rows

    float4 pA[2], pB[4];
    {   // preload first chunk
        int kc = ks*CPK;
        #pragma unroll
        for (int it=0; it<2; it++)
            pA[it] = *reinterpret_cast<const float4*>(W + (size_t)(m0 + a_m0 + it*32)*KTOT + kc*32 + a_kq);
        #pragma unroll
        for (int it=0; it<4; it++)
            pB[it] = *reinterpret_cast<const float4*>(Act + (size_t)(kc*32 + b_kr0 + it*8)*4096 + b0 + b_nq);
    }

    for (int c = 0; c < CPK; c++){
        // ---- store prefetched chunk into smem (A pre-split hi/lo) ----
        #pragma unroll
        for (int it=0; it<2; it++){
            int m = a_m0 + it*32;
            int tm = m >> 4, row = m & 15;
            float vv[4] = {pA[it].x, pA[it].y, pA[it].z, pA[it].w};
            #pragma unroll
            for (int j=0;j<4;j++){
                int k = a_kq + j, tk = k >> 3, col = k & 7;
                int lane_s = ((row & 7) << 2) | (col & 3);
                int reg = ((row >> 3) & 1) | ((col >> 2) << 1);
                int off = (tm*4 + tk)*132 + lane_s*4 + reg;
                u32 hi = cvt_tf32(vv[j]);
                *reinterpret_cast<u32*>(&sAh[off]) = hi;
                *reinterpret_cast<u32*>(&sAl[off]) = cvt_tf32(vv[j] - __uint_as_float(hi));
            }
        }
        #pragma unroll
        for (int it=0; it<4; it++){
            int kr = b_kr0 + it*8;
            int tk = kr >> 3, rowk = kr & 7;
            float vv[4] = {pB[it].x, pB[it].y, pB[it].z, pB[it].w};
            #pragma unroll
            for (int j=0;j<4;j++){
                int n = b_nq + j;
                sB[((n>>3)*4 + tk)*66 + (((n&7)<<2)|(rowk&3))*2 + (rowk>>2)] = vv[j];
            }
        }
        __syncthreads();

        // ---- prefetch next chunk (LDG latency overlaps MMA phase) ----
        if (c + 1 < CPK){
            int kc = ks*CPK + c + 1;
            #pragma unroll
            for (int it=0; it<2; it++)
                pA[it] = *reinterpret_cast<const float4*>(W + (size_t)(m0 + a_m0 + it*32)*KTOT + kc*32 + a_kq);
            #pragma unroll
            for (int it=0; it<4; it++)
                pB[it] = *reinterpret_cast<const float4*>(Act + (size_t)(kc*32 + b_kr0 + it*8)*4096 + b0 + b_nq);
        }

        // ---- MMA phase ----
        #pragma unroll
        for (int tk=0; tk<4; tk++){
            u32 afh[2][4], afl[2][4];
            u32 bfh[4][2], bfl[4][2];
            #pragma unroll
            for (int i=0;i<2;i++){
                int base = ((wm*2+i)*4 + tk)*132 + lane*4;
                const float4 h4 = *reinterpret_cast<const float4*>(&sAh[base]);
                const float4 l4 = *reinterpret_cast<const float4*>(&sAl[base]);
                afh[i][0]=__float_as_uint(h4.x); afh[i][1]=__float_as_uint(h4.y);
                afh[i][2]=__float_as_uint(h4.z); afh[i][3]=__float_as_uint(h4.w);
                afl[i][0]=__float_as_uint(l4.x); afl[i][1]=__float_as_uint(l4.y);
                afl[i][2]=__float_as_uint(l4.z); afl[i][3]=__float_as_uint(l4.w);
            }
            #pragma unroll
            for (int j=0;j<4;j++){
                const float2 t2 = *reinterpret_cast<const float2*>(&sB[((wn*4+j)*4 + tk)*66 + lane*2]);
                float tv[2] = {t2.x, t2.y};
                #pragma unroll
                for (int q=0;q<2;q++){
                    u32 hi = cvt_tf32(tv[q]);
                    bfh[j][q] = hi;
                    bfl[j][q] = cvt_tf32(tv[q] - __uint_as_float(hi));
                }
            }
            #pragma unroll
            for (int i=0;i<2;i++)
                #pragma unroll
                for (int j=0;j<4;j++){
                    asm volatile(
                        "mma.sync.aligned.m16n8k8.row.col.f32.tf32.tf32.f32 "
                        "{%0,%1,%2,%3}, {%4,%5,%6,%7}, {%8,%9}, {%0,%1,%2,%3};"
                        : "+f"(acc[i][j][0]), "+f"(acc[i][j][1]), "+f"(acc[i][j][2]), "+f"(acc[i][j][3])
                        : "r"(afh[i][0]), "r"(afh[i][1]), "r"(afh[i][2]), "r"(afh[i][3]),
                          "r"(bfl[j][0]), "r"(bfl[j][1]));
                    asm volatile(
                        "mma.sync.aligned.m16n8k8.row.col.f32.tf32.tf32.f32 "
                        "{%0,%1,%2,%3}, {%4,%5,%6,%7}, {%8,%9}, {%0,%1,%2,%3};"
                        : "+f"(acc[i][j][0]), "+f"(acc[i][j][1]), "+f"(acc[i][j][2]), "+f"(acc[i][j][3])
                        : "r"(afl[i][0]), "r"(afl[i][1]), "r"(afl[i][2]), "r"(afl[i][3]),
                          "r"(bfh[j][0]), "r"(bfh[j][1]));
                    asm volatile(
                        "mma.sync.aligned.m16n8k8.row.col.f32.tf32.tf32.f32 "
                        "{%0,%1,%2,%3}, {%4,%5,%6,%7}, {%8,%9}, {%0,%1,%2,%3};"
                        : "+f"(acc[i][j][0]), "+f"(acc[i][j][1]), "+f"(acc[i][j][2]), "+f"(acc[i][j][3])
                        : "r"(afh[i][0]), "r"(afh[i][1]), "r"(afh[i][2]), "r"(afh[i][3]),
                          "r"(bfh[j][0]), "r"(bfh[j][1]));
                }
        }
        __syncthreads();
    }

    #pragma unroll
    for (int i=0;i<2;i++){
        int mA = m0 + wm*32 + i*16 + group;
        int mB = mA + 8;
        float bA = (KSPLIT==1) ? bias[mA] : 0.0f;
        float bB = (KSPLIT==1) ? bias[mB] : 0.0f;
        #pragma unroll
        for (int j=0;j<4;j++){
            int n = b0 + wn*32 + j*8 + tig*2;
            float r0 = acc[i][j][0] + bA, r1 = acc[i][j][1] + bA;
            float r2 = acc[i][j][2] + bB, r3 = acc[i][j][3] + bB;
            if (RELU && KSPLIT==1){
                r0 = fmaxf(r0,0.0f); r1 = fmaxf(r1,0.0f);
                r2 = fmaxf(r2,0.0f); r3 = fmaxf(r3,0.0f);
            }
            *reinterpret_cast<float2*>(out + (size_t)mA*4096 + n) = make_float2(r0, r1);
            *reinterpret_cast<float2*>(out + (size_t)mB*4096 + n) = make_float2(r2, r3);
        }
    }
}

// ---------------- scalar conv kernel (R0-proven variant) ----------------
template<int CIN,int COUT,int K,int HIN,int WIN,int HOUT,int WOUT,int STRIDE,int PAD,
         bool DECONV,int OCC,int VEC,int ICC,int ACT>
__global__ void __launch_bounds__(256) convk(
    const float* __restrict__ in, const float* __restrict__ wt,
    const float* __restrict__ bias, float* __restrict__ out)
{
    static_assert(CIN % ICC == 0, "ICC must divide CIN");
    constexpr int KK = K*K;
    const int p  = blockIdx.y;
    const int oy = p / WOUT, ox = p % WOUT;
    const int oc0 = blockIdx.z * OCC;
    const int b  = (blockIdx.x * 256 + threadIdx.x) * VEC;

    __shared__ u64 sw[OCC*ICC*KK];

    u64 acc[OCC][VEC/2];
    #pragma unroll
    for (int j=0;j<OCC;j++){
        float bv = bias[oc0 + j];
        u64 bp = pack2(bv,bv);
        #pragma unroll
        for (int v=0;v<VEC/2;v++) acc[j][v] = bp;
    }

    for (int ic0 = 0; ic0 < CIN; ic0 += ICC){
        __syncthreads();
        for (int i = threadIdx.x; i < OCC*ICC*KK; i += 256){
            int jo = i / (ICC*KK);
            int ic = (i / KK) % ICC;
            int kk = i % KK;
            int g  = DECONV ? (((ic0+ic)*COUT + (oc0+jo))*KK + kk)
                            : (((oc0+jo)*CIN + (ic0+ic))*KK + kk);
            float w = wt[g];
            sw[i] = pack2(w, w);
        }
        __syncthreads();

        #pragma unroll
        for (int ky=0; ky<K; ky++){
            int iy; bool vy;
            if (DECONV){ int t = oy + PAD - ky; vy = (t>=0) && ((t % STRIDE)==0); iy = t / STRIDE; vy = vy && (iy < HIN); }
            else       { iy = oy*STRIDE - PAD + ky; vy = (iy>=0) && (iy < HIN); }
            if (!vy) continue;
            #pragma unroll
            for (int kx=0; kx<K; kx++){
                int ix; bool vx;
                if (DECONV){ int t = ox + PAD - kx; vx = (t>=0) && ((t % STRIDE)==0); ix = t / STRIDE; vx = vx && (ix < WIN); }
                else       { ix = ox*STRIDE - PAD + kx; vx = (ix>=0) && (ix < WIN); }
                if (!vx) continue;
                const int kk = ky*K + kx;
                const float* ipbase = in + ((size_t)(iy*WIN + ix))*BATCH + b;
                #pragma unroll 4
                for (int ic=0; ic<ICC; ic++){
                    const float* ip = ipbase + (size_t)(ic0+ic)*(HIN*WIN)*BATCH;
                    u64 v[VEC/2];
                    if constexpr (VEC == 4){
                        ulonglong2 u = *reinterpret_cast<const ulonglong2*>(ip);
                        v[0] = u.x; v[1] = u.y;
                    } else {
                        v[0] = *reinterpret_cast<const u64*>(ip);
                    }
                    #pragma unroll
                    for (int j=0;j<OCC;j++){
                        u64 wv = sw[(j*ICC + ic)*KK + kk];
                        #pragma unroll
                        for (int h=0; h<VEC/2; h++) acc[j][h] = fma2(v[h], wv, acc[j][h]);
                    }
                }
            }
        }
    }

    #pragma unroll
    for (int j=0;j<OCC;j++){
        float vals[VEC];
        #pragma unroll
        for (int h=0; h<VEC/2; h++){
            float a_, b_; unpack2(acc[j][h], a_, b_);
            vals[2*h] = a_; vals[2*h+1] = b_;
        }
        #pragma unroll
        for (int q=0; q<VEC; q++){
            if (ACT == 1) vals[q] = fmaxf(vals[q], 0.0f);
            else if (ACT == 2) vals[q] = 1.0f / (1.0f + __expf(-vals[q]));
        }
        float* op = out + ((size_t)((oc0+j)*(HOUT*WOUT) + p))*BATCH + b;
        if constexpr (VEC == 4) *reinterpret_cast<float4*>(op) = make_float4(vals[0],vals[1],vals[2],vals[3]);
        else                    *reinterpret_cast<float2*>(op) = make_float2(vals[0],vals[1]);
    }
}

// ---------------- fused fc1-reduce + mu/ls heads (verified R15/R16) ----------------
__global__ void __launch_bounds__(256) muls_k(
    const float* __restrict__ part, const float* __restrict__ bfc1,
    const float* __restrict__ wmu, const float* __restrict__ bmu,
    const float* __restrict__ wls, const float* __restrict__ bls,
    float* __restrict__ muB, float* __restrict__ lsB)
{
    __shared__ u64 swm[4*256];
    __shared__ u64 swl[4*256];
    __shared__ float sbias[256];
    const int l0 = blockIdx.z * 4;
    for (int i = threadIdx.x; i < 4*256; i += 256){
        int l = i >> 8, k = i & 255;
        float a = wmu[(l0+l)*256 + k]; swm[i] = pack2(a,a);
        float c = wls[(l0+l)*256 + k]; swl[i] = pack2(c,c);
    }
    if (threadIdx.x < 256) sbias[threadIdx.x] = bfc1[threadIdx.x];
    __syncthreads();

    const int b = (blockIdx.x*256 + threadIdx.x) * 4;
    u64 am[4][2], al[4][2];
    #pragma unroll
    for (int j=0;j<4;j++){
        float bm = bmu[l0+j], bl2 = bls[l0+j];
        am[j][0] = pack2(bm,bm); am[j][1] = am[j][0];
        al[j][0] = pack2(bl2,bl2); al[j][1] = al[j][0];
    }
    const float* p0 = part;
    const float* p1 = part + (size_t)256*4096;
    #pragma unroll 2
    for (int k=0;k<256;k++){
        float4 q0 = *reinterpret_cast<const float4*>(p0 + (size_t)k*4096 + b);
        float4 q1 = *reinterpret_cast<const float4*>(p1 + (size_t)k*4096 + b);
        float bv = sbias[k];
        float h0 = fmaxf(q0.x + q1.x + bv, 0.0f);
        float h1 = fmaxf(q0.y + q1.y + bv, 0.0f);
        float h2 = fmaxf(q0.z + q1.z + bv, 0.0f);
        float h3 = fmaxf(q0.w + q1.w + bv, 0.0f);
        u64 hx = pack2(h0, h1), hy = pack2(h2, h3);
        #pragma unroll
        for (int j=0;j<4;j++){
            u64 wm = swm[j*256 + k], wl = swl[j*256 + k];
            am[j][0] = fma2(hx, wm, am[j][0]);
            am[j][1] = fma2(hy, wm, am[j][1]);
            al[j][0] = fma2(hx, wl, al[j][0]);
            al[j][1] = fma2(hy, wl, al[j][1]);
        }
    }
    #pragma unroll
    for (int j=0;j<4;j++){
        float m0,m1,m2,m3, s0,s1,s2,s3;
        unpack2(am[j][0], m0,m1); unpack2(am[j][1], m2,m3);
        unpack2(al[j][0], s0,s1); unpack2(al[j][1], s2,s3);
        float* mp = muB + (size_t)(l0+j)*4096 + b;
        float* sp = lsB + (size_t)(l0+j)*4096 + b;
        *reinterpret_cast<float4*>(mp) = make_float4(m0,m1,m2,m3);
        *reinterpret_cast<float4*>(sp) = make_float4(s0,s1,s2,s3);
    }
}

// ---------------- specialized deconv3 (32->1, sigmoid) + fused output transpose ----
__global__ void __launch_bounds__(256,4) deconv3_k(
    const float* __restrict__ in, const float* __restrict__ wt,
    const float* __restrict__ bias, float* __restrict__ out) // out: [B][784]
{
    __shared__ __align__(16) u64 sw[32*16];
    for (int i = threadIdx.x; i < 512; i += 256){ float w = wt[i]; sw[i] = pack2(w,w); }
    __syncthreads();

    const int t  = blockIdx.y % 7;
    const int oy = blockIdx.y / 7;
    const int b  = (blockIdx.x*256 + threadIdx.x) * 4;

    float bv = bias[0];
    u64 bp = pack2(bv,bv);
    u64 acc[4][2];
    #pragma unroll
    for (int p2=0;p2<4;p2++){ acc[p2][0]=bp; acc[p2][1]=bp; }

    const bool v0 = (2*t-1) >= 0;
    const bool v3 = (2*t+2) < 14;
    const int ky0 = (oy + 1) & 1;

    #pragma unroll
    for (int kyi=0; kyi<2; kyi++){
        const int ky = ky0 + 2*kyi;
        const int iy = (oy + 1 - ky) >> 1;
        if (iy < 0 || iy >= 14) continue;
        for (int ic=0; ic<32; ic++){
            const float* ipb = in + ((size_t)(ic*196 + iy*14 + 2*t - 1))*BATCH + b;
            u64 L[4][2];
            #pragma unroll
            for (int k=0;k<4;k++){
                bool valid = (k==0) ? v0 : (k==3 ? v3 : true);
                if (valid){
                    ulonglong2 u = *reinterpret_cast<const ulonglong2*>(ipb + (size_t)k*BATCH);
                    L[k][0]=u.x; L[k][1]=u.y;
                } else { L[k][0]=0; L[k][1]=0; }
            }
            const u64* wb = &sw[ic*16 + ky*4];
            u64 w0=wb[0], w1=wb[1], w2=wb[2], w3=wb[3];
            #pragma unroll
            for (int h=0;h<2;h++){
                acc[0][h] = fma2(L[1][h], w1, acc[0][h]);
                acc[0][h] = fma2(L[0][h], w3, acc[0][h]);
                acc[1][h] = fma2(L[2][h], w0, acc[1][h]);
                acc[1][h] = fma2(L[1][h], w2, acc[1][h]);
                acc[2][h] = fma2(L[2][h], w1, acc[2][h]);
                acc[2][h] = fma2(L[1][h], w3, acc[2][h]);
                acc[3][h] = fma2(L[3][h], w0, acc[3][h]);
                acc[3][h] = fma2(L[2][h], w2, acc[3][h]);
            }
        }
    }

    float vals[4][4];
    #pragma unroll
    for (int p2=0;p2<4;p2++){
        unpack2(acc[p2][0], vals[p2][0], vals[p2][1]);
        unpack2(acc[p2][1], vals[p2][2], vals[p2][3]);
        #pragma unroll
        for (int q=0;q<4;q++) vals[p2][q] = 1.0f / (1.0f + __expf(-vals[p2][q]));
    }
    const int pbase = oy*28 + 4*t;
    #pragma unroll
    for (int bi=0; bi<4; bi++){
        float* op = out + (size_t)(b + bi)*784 + pbase;
        *reinterpret_cast<float4*>(op) = make_float4(vals[0][bi], vals[1][bi], vals[2][bi], vals[3][bi]);
    }
}

// ---------------- latent: 100-step recursion ----------------
__global__ void latent_k(const float* __restrict__ mu, const float* __restrict__ ls,
                         const float* __restrict__ eps, float* __restrict__ zl,
                         float* __restrict__ outMu, float* __restrict__ outLv)
{
    int i = blockIdx.x*256 + threadIdx.x;
    if (i >= 20*BATCH) return;
    int l = i / BATCH, b = i % BATCH;
    float m = mu[i];
    float s = ls[i];
    outMu[(size_t)b*20 + l] = m;
    outLv[(size_t)b*20 + l] = s;
    float mr = m, sr = s;
    #pragma unroll 5
    for (int k=0;k<100;k++){
        mr = mr + 0.1f*mr;
        sr = sr + 0.05f*(__expf(sr) - 1.0f);
    }
    zl[i] = eps[(size_t)b*20 + l] * __expf(0.5f*sr) + mr;
}

extern "C" void kernel_launch(void* const* d_in, const int* in_sizes, int n_in,
                              void* d_out, int out_size)
{
    const float* x    = (const float*)d_in[0];
    const float* eps  = (const float*)d_in[1];
    const float* w_c1 = (const float*)d_in[2];  const float* b_c1 = (const float*)d_in[3];
    const float* w_c2 = (const float*)d_in[4];  const float* b_c2 = (const float*)d_in[5];
    const float* w_c3 = (const float*)d_in[6];  const float* b_c3 = (const float*)d_in[7];
    const float* w_fc1= (const float*)d_in[8];  const float* b_fc1= (const float*)d_in[9];
    const float* w_mu = (const float*)d_in[10]; const float* b_mu = (const float*)d_in[11];
    const float* w_ls = (const float*)d_in[12]; const float* b_ls = (const float*)d_in[13];
    const float* w_fc2= (const float*)d_in[14]; const float* b_fc2= (const float*)d_in[15];
    const float* w_fc3= (const float*)d_in[16]; const float* b_fc3= (const float*)d_in[17];
    const float* w_d1 = (const float*)d_in[18]; const float* b_d1 = (const float*)d_in[19];
    const float* w_d2 = (const float*)d_in[20]; const float* b_d2 = (const float*)d_in[21];
    const float* w_d3 = (const float*)d_in[22]; const float* b_d3 = (const float*)d_in[23];
    float* out = (float*)d_out;

    float* S = nullptr;
    cudaGetSymbolAddress((void**)&S, g_scratch);

    float* xT = S + OFF_XT;
    float* a1 = S + OFF_A1;
    float* a2 = S + OFF_A2;
    float* a3 = S + OFF_A3;
    float* muB= S + OFF_MU;
    float* lsB= S + OFF_LS;
    float* zl = S + OFF_ZL;
    float* d1h= S + OFF_D1;
    float* d2h= S + OFF_D2;
    float* d3 = S + OFF_D3;
    float* d4 = S + OFF_D4;
    float* fcp= S + OFF_FCP;

    float* outMu = out + (size_t)BATCH*784;
    float* outLv = outMu + (size_t)BATCH*20;

    dim3 tb(32,32);
    transpose_k<<<dim3(25,128), tb>>>(x, xT, 4096, 784);

    // encoder (best-measured scalar conv configs)          OCC VEC ICC ACT
    convk<1,  32, 4, 28,28, 14,14, 2,1, false, 16,4, 1,  1><<<dim3(4,196,2), 256>>>(xT,  w_c1, b_c1, a1);
    convk<32, 32, 4, 14,14, 7, 7,  2,1, false, 8, 4, 32, 1><<<dim3(4,49, 4), 256>>>(a1,  w_c2, b_c2, a2);
    convk<32, 64, 3, 7, 7,  4, 4,  2,1, false, 8, 4, 32, 1><<<dim3(4,16, 8), 256>>>(a2,  w_c3, b_c3, a3);

    // fc1 on pipelined mma.sync tf32x2 split, split-K=2
    gemm_mma<1024,false,256,2><<<dim3(32,4,2), 256>>>(a3, w_fc1, b_fc1, fcp);

    // fused fc1-reduce + mu/ls heads
    muls_k<<<dim3(4,1,5), 256>>>(fcp, b_fc1, w_mu, b_mu, w_ls, b_ls, muB, lsB);

    latent_k<<<(20*BATCH + 255)/256, 256>>>(muB, lsB, eps, zl, outMu, outLv);

    // decoder
    convk<20, 256, 1, 1,1,  1, 1,  1,0, false, 16,4, 20, 1><<<dim3(4,1, 16), 256>>>(zl,  w_fc2,b_fc2,d1h);
    gemm_mma<256,true,1024,1><<<dim3(32,16,1), 256>>>(d1h, w_fc3, b_fc3, d2h);

    convk<64, 32, 3, 4, 4,  7, 7,  2,1, true,  8, 4, 64, 1><<<dim3(4,49, 4), 256>>>(d2h, w_d1, b_d1, d3);
    convk<32, 32, 4, 7, 7,  14,14, 2,1, true,  8, 4, 32, 1><<<dim3(4,196,4), 256>>>(d3,  w_d2, b_d2, d4);
    deconv3_k<<<dim3(4,196), 256>>>(d4, w_d3, b_d3, out);
}